// round 15
// baseline (speedup 1.0000x reference)
#include <cuda_runtime.h>
#include <cuda_fp16.h>
#include <cstdint>

// B=2, N=1024, C=128, H1=128, H2=64
//   aL[b,i,h] = x[b,i]@W1[:C] + b1 ; aR[b,j,h] = x[b,j]@W1[C:]
//   y[b,i,j] = relu(relu(aL_i + aR_j) @ W2 + b2) @ W3 + b3   (j>i else 0)
// R15 (base = R14, 65.6us; regs=255 -> spills):
//  1) first-kstep MMAs use C=0 and WRITE acc (no 128-MOV zero init per tile)
//  2) w2r regs cut to nt0..1 (32 regs) -> ~220 regs total, spills gone
//  3) epilogue fma chains split into 2 independent partials (ILP)

#define Bb 2
#define Nn 1024
#define Cc 128
#define H1 128
#define H2 64

#define NACT4 16640    // active 4x16 warp-tiles: 2 * 8320
#define HALF4 8320

__device__ __align__(16) __half2 g_aLh[Bb * Nn * 64];
__device__ __align__(16) __half2 g_aRh[Bb * Nn * 64];
__device__ __align__(16) __half2 g_W2h[H2 * 64];
__device__ unsigned g_cnt = 0u;
__device__ unsigned g_done = 0u;

__device__ __forceinline__ int slotperm(int j) {
    int jj = j & 7;
    return (j & ~7) | (jj < 4 ? (jj << 1) : (((jj - 4) << 1) | 1));
}

__device__ __forceinline__ uint32_t h2_relu_add(uint32_t x, uint32_t y) {
    __half2 a = *reinterpret_cast<__half2*>(&x);
    __half2 b = *reinterpret_cast<__half2*>(&y);
    __half2 r = __hmax2(__hadd2(a, b), __float2half2_rn(0.f));
    return *reinterpret_cast<uint32_t*>(&r);
}

__device__ __forceinline__ void mma_f16(float c[4], const uint32_t a[4],
                                        uint32_t b0, uint32_t b1) {
    asm volatile(
        "mma.sync.aligned.m16n8k16.row.col.f32.f16.f16.f32 "
        "{%0,%1,%2,%3},{%4,%5,%6,%7},{%8,%9},{%0,%1,%2,%3};"
        : "+f"(c[0]), "+f"(c[1]), "+f"(c[2]), "+f"(c[3])
        : "r"(a[0]), "r"(a[1]), "r"(a[2]), "r"(a[3]), "r"(b0), "r"(b1));
}

// first-kstep variant: D = A*B + 0  (writes acc, no prior init needed)
__device__ __forceinline__ void mma_f16_zero(float c[4], const uint32_t a[4],
                                             uint32_t b0, uint32_t b1) {
    asm volatile(
        "mma.sync.aligned.m16n8k16.row.col.f32.f16.f16.f32 "
        "{%0,%1,%2,%3},{%4,%5,%6,%7},{%8,%9},{%10,%10,%10,%10};"
        : "=f"(c[0]), "=f"(c[1]), "=f"(c[2]), "=f"(c[3])
        : "r"(a[0]), "r"(a[1]), "r"(a[2]), "r"(a[3]), "r"(b0), "r"(b1),
          "f"(0.f));
}

__device__ __forceinline__ uint32_t smem_u32(const void* p) {
    uint32_t a;
    asm("{ .reg .u64 t; cvta.to.shared.u64 t, %1; cvt.u32.u64 %0, t; }"
        : "=r"(a) : "l"(p));
    return a;
}
__device__ __forceinline__ void cpasync16(uint32_t dst, const void* src) {
    asm volatile("cp.async.cg.shared.global [%0], [%1], 16;"
                 :: "r"(dst), "l"(src));
}
#define CP_COMMIT() asm volatile("cp.async.commit_group;" ::: "memory")
#define CP_WAIT1()  asm volatile("cp.async.wait_group 1;" ::: "memory")

#define AR_STRIDE 34
#define W2_STRIDE 34

#define SM_B2_OFF   17408
#define SM_W3_OFF   17664
#define SM_WARP_OFF 17920
#define WARP_BYTES  10752
#define SMEM_TOTAL  (SM_WARP_OFF + 8 * WARP_BYTES)   // 103936

__device__ __forceinline__ void decode4(int a, int& b, int& i0, int& j0) {
    b = (a >= HALF4);
    int aa = a - (b ? HALF4 : 0);
    int g = (int)((258.f - sqrtf(66564.f - 8.f * (float)aa)) * 0.25f);
    if (g < 0) g = 0;
    if (g > 63) g = 63;
    while (g < 63 && 258 * (g + 1) - 2 * (g + 1) * (g + 1) <= aa) g++;
    while (g > 0 && 258 * g - 2 * g * g > aa) g--;
    int rem = aa - (258 * g - 2 * g * g);
    int cnt = 64 - g;
    int io = rem / cnt;
    j0 = (g + rem - io * cnt) << 4;
    i0 = (g << 4) + (io << 2);
}

__global__ void __launch_bounds__(256)
fused_kernel(const float* __restrict__ x,
             const float* __restrict__ W1,
             const float* __restrict__ b1,
             const float* __restrict__ W2,
             const float* __restrict__ b2,
             const float* __restrict__ W3,
             const float* __restrict__ b3,
             float* __restrict__ out) {
    extern __shared__ char smraw[];

    const int tid = threadIdx.x;
    const int bid = blockIdx.x;
    const int nblk = gridDim.x;
    const int wid = tid >> 5;
    const int lane = tid & 31;
    const int p = lane >> 2;
    const int q = lane & 3;

    // ======================= PHASE A: prep =======================
    {
        float* sx = (float*)smraw;               // [14][128]
        float* res = (float*)(smraw + 7168);     // [14][256]
        const int r0 = bid * 14;
        const int nrows = min(14, Bb * Nn - r0);

        if (nrows > 0) {
            const float4* x4 = (const float4*)x;
            const int nchunks = nrows * 32;
#pragma unroll
            for (int u = 0; u < 2; u++) {
                int c = tid + 256 * u;
                if (c < nchunks)
                    ((float4*)sx)[c] = x4[r0 * 32 + c];
            }
            __syncthreads();

            const int side = tid >> 7;
            const int h = tid & 127;
            const float* Wp = W1 + (side ? (Cc * H1 + h) : h);
            float acc[14];
            const float init = side ? 0.f : b1[h];
#pragma unroll
            for (int r = 0; r < 14; r++) acc[r] = init;

#pragma unroll 4
            for (int c = 0; c < Cc; c += 4) {
                float w0 = __ldg(&Wp[(c + 0) * H1]);
                float w1 = __ldg(&Wp[(c + 1) * H1]);
                float w2 = __ldg(&Wp[(c + 2) * H1]);
                float w3 = __ldg(&Wp[(c + 3) * H1]);
#pragma unroll
                for (int r = 0; r < 14; r++) {
                    const float* sxr = sx + r * Cc + c;
                    float4 sv = *(const float4*)sxr;
                    float a = acc[r];
                    a = fmaf(sv.x, w0, a);
                    a = fmaf(sv.y, w1, a);
                    a = fmaf(sv.z, w2, a);
                    a = fmaf(sv.w, w3, a);
                    acc[r] = a;
                }
            }
#pragma unroll
            for (int r = 0; r < 14; r++) res[r * 256 + side * 128 + h] = acc[r];
            __syncthreads();

#pragma unroll
            for (int u = 0; u < 7; u++) {
                int idx = tid + 256 * u;
                int row = idx >> 7;
                if (row < nrows) {
                    int rem = idx & 127;
                    int sd = rem >> 6;
                    int j = rem & 63;
                    __half2 v = __floats2half2_rn(res[row * 256 + sd * 128 + 2 * j],
                                                  res[row * 256 + sd * 128 + 2 * j + 1]);
                    (sd ? g_aRh : g_aLh)[(size_t)(r0 + row) * 64 + slotperm(j)] = v;
                }
            }
        } else {
            for (int idx = (bid - 147) * 256 + tid; idx < H2 * 64;
                 idx += (nblk - 147) * 256) {
                int n = idx >> 6;
                int j = idx & 63;
                g_W2h[n * 64 + slotperm(j)] =
                    __floats2half2_rn(W2[(2 * j) * H2 + n],
                                      W2[(2 * j + 1) * H2 + n]);
            }
        }

        // zero masked region (rows: j < 16*(i>>4))
        {
            float4* out4 = (float4*)out;
            const float4 z4 = make_float4(0.f, 0.f, 0.f, 0.f);
            for (int r = bid; r < Bb * Nn; r += nblk) {
                int i = r & (Nn - 1);
                int n4 = 4 * (i >> 4);
                float4* dst = out4 + ((size_t)r << 8);
                for (int c = tid; c < n4; c += 256) dst[c] = z4;
            }
        }
    }

    // =================== grid barrier (spin, self-resetting) ===================
    __threadfence();
    __syncthreads();
    if (tid == 0) {
        atomicAdd(&g_cnt, 1u);
        while (atomicAdd(&g_cnt, 0u) < (unsigned)nblk) __nanosleep(64);
    }
    __syncthreads();

    // ======================= PHASE B: warp-autonomous pair GEMM =======================
    uint2* w2s = (uint2*)smraw;
    float* b2s = (float*)(smraw + SM_B2_OFF);
    float* w3s = (float*)(smraw + SM_W3_OFF);

    {
        const uint2* gW2 = (const uint2*)g_W2h;
        for (int i = tid; i < H2 * 32; i += 256) {
            int r = i >> 5, c = i & 31;
            w2s[r * W2_STRIDE + c] = gW2[i];
        }
        if (tid < H2) {
            b2s[tid] = b2[tid];
            w3s[tid] = W3[tid];
        }
    }
    const float b3v = __ldg(&b3[0]);
    __syncthreads();      // last CTA-wide barrier

    // persistent W2 fragments nt 0..1 only (32 regs; nt 2..7 from smem)
    uint32_t w2r[8][2][2];
#pragma unroll
    for (int ks = 0; ks < 8; ks++)
#pragma unroll
        for (int ntl = 0; ntl < 2; ntl++) {
            uint2 bb = w2s[(ntl * 8 + p) * W2_STRIDE + 4 * ks + q];
            w2r[ks][ntl][0] = bb.x;
            w2r[ks][ntl][1] = bb.y;
        }

    char* wb = smraw + SM_WARP_OFF + wid * WARP_BYTES;
    const uint32_t wL32 = smem_u32(wb);
    const uint32_t wR32 = wL32 + 2048;
    uint2* aLbase = (uint2*)wb;
    uint2* aRbase = (uint2*)(wb + 2048);

    auto issue_stage = [&](int bf, int b, int i0, int j0) {
        const uint4* srcL = (const uint4*)(g_aLh + ((size_t)((b << 10) + i0) << 6));
        const uint4* srcR = (const uint4*)(g_aRh + ((size_t)((b << 10) + j0) << 6));
        uint32_t dL = wL32 + (uint32_t)bf * 1024u;
        uint32_t dR = wR32 + (uint32_t)bf * 4352u;
        cpasync16(dL + (uint32_t)lane * 16u, srcL + lane);
        cpasync16(dL + (uint32_t)(lane + 32) * 16u, srcL + lane + 32);
#pragma unroll
        for (int u = 0; u < 8; u++) {
            int c = lane + 32 * u;
            int row = c >> 4, col = c & 15;
            cpasync16(dR + (uint32_t)(row * 17 + col) * 16u, srcR + c);
        }
    };

    int a = bid * 8 + wid;
    const int astep = nblk * 8;
    int buf = 0;
    int curB = 0, curI0 = 0, curJ0 = 0;
    if (a < NACT4) {
        decode4(a, curB, curI0, curJ0);
        issue_stage(0, curB, curI0, curJ0);
    }
    CP_COMMIT();

    for (; a < NACT4; a += astep) {
        const int b  = curB;
        const int i0 = curI0;
        const int j0 = curJ0;

        {
            int an = a + astep;
            if (an < NACT4) {
                decode4(an, curB, curI0, curJ0);
                issue_stage(buf ^ 1, curB, curI0, curJ0);
            }
            CP_COMMIT();
        }
        CP_WAIT1();
        __syncwarp();

        const uint2* aLb = aLbase + buf * 128;
        const uint2* aRb = aRbase + buf * 544;

        float acc[4][8][4];   // written by ks=0 MMAs (zero-C), no init

        uint2 Rp_c, Rp8_c, La_c0, La_c1, La_c2, La_c3;
        {
            const int kf = q;
            Rp_c  = aRb[p * AR_STRIDE + kf];
            Rp8_c = aRb[(p + 8) * AR_STRIDE + kf];
            La_c0 = aLb[0 * 32 + kf];
            La_c1 = aLb[1 * 32 + kf];
            La_c2 = aLb[2 * 32 + kf];
            La_c3 = aLb[3 * 32 + kf];
        }
#pragma unroll
        for (int ks = 0; ks < 8; ks++) {
            uint2 Rp_n, Rp8_n, La_n0, La_n1, La_n2, La_n3;
            if (ks < 7) {
                const int kf = 4 * (ks + 1) + q;
                Rp_n  = aRb[p * AR_STRIDE + kf];
                Rp8_n = aRb[(p + 8) * AR_STRIDE + kf];
                La_n0 = aLb[0 * 32 + kf];
                La_n1 = aLb[1 * 32 + kf];
                La_n2 = aLb[2 * 32 + kf];
                La_n3 = aLb[3 * 32 + kf];
            }

            uint32_t a4[4][4];
            {
                uint2 Ls[4] = {La_c0, La_c1, La_c2, La_c3};
#pragma unroll
                for (int mt = 0; mt < 4; mt++) {
                    a4[mt][0] = h2_relu_add(Ls[mt].x, Rp_c.x);
                    a4[mt][1] = h2_relu_add(Ls[mt].x, Rp8_c.x);
                    a4[mt][2] = h2_relu_add(Ls[mt].y, Rp_c.y);
                    a4[mt][3] = h2_relu_add(Ls[mt].y, Rp8_c.y);
                }
            }

            if (ks == 0) {
#pragma unroll
                for (int ntl = 0; ntl < 2; ntl++)
#pragma unroll
                    for (int mt = 0; mt < 4; mt++)
                        mma_f16_zero(acc[mt][ntl], a4[mt],
                                     w2r[0][ntl][0], w2r[0][ntl][1]);
#pragma unroll
                for (int ntl = 2; ntl < 8; ntl++) {
                    uint2 bb = w2s[(ntl * 8 + p) * W2_STRIDE + q];
#pragma unroll
                    for (int mt = 0; mt < 4; mt++)
                        mma_f16_zero(acc[mt][ntl], a4[mt], bb.x, bb.y);
                }
            } else {
#pragma unroll
                for (int ntl = 0; ntl < 2; ntl++)
#pragma unroll
                    for (int mt = 0; mt < 4; mt++)
                        mma_f16(acc[mt][ntl], a4[mt],
                                w2r[ks][ntl][0], w2r[ks][ntl][1]);
#pragma unroll
                for (int ntl = 2; ntl < 8; ntl++) {
                    uint2 bb = w2s[(ntl * 8 + p) * W2_STRIDE + 4 * ks + q];
#pragma unroll
                    for (int mt = 0; mt < 4; mt++)
                        mma_f16(acc[mt][ntl], a4[mt], bb.x, bb.y);
                }
            }

            Rp_c = Rp_n; Rp8_c = Rp8_n;
            La_c0 = La_n0; La_c1 = La_n1; La_c2 = La_n2; La_c3 = La_n3;
        }

        // epilogue: y = b3 + sum_g relu(D+b2)*W3 ; 2-way ILP partials
#pragma unroll
        for (int mt = 0; mt < 4; mt++) {
            float sl0 = 0.f, sl1 = 0.f, sh0 = 0.f, sh1 = 0.f;
#pragma unroll
            for (int nt = 0; nt < 8; nt += 2) {
                int g0 = nt * 8 + 2 * q;
                int g1 = (nt + 1) * 8 + 2 * q;
                float b200 = b2s[g0], b201 = b2s[g0 + 1];
                float w300 = w3s[g0], w301 = w3s[g0 + 1];
                float b210 = b2s[g1], b211 = b2s[g1 + 1];
                float w310 = w3s[g1], w311 = w3s[g1 + 1];
                sl0 = fmaf(fmaxf(acc[mt][nt][0] + b200, 0.f), w300, sl0);
                sl0 = fmaf(fmaxf(acc[mt][nt][1] + b201, 0.f), w301, sl0);
                sh0 = fmaf(fmaxf(acc[mt][nt][2] + b200, 0.f), w300, sh0);
                sh0 = fmaf(fmaxf(acc[mt][nt][3] + b201, 0.f), w301, sh0);
                sl1 = fmaf(fmaxf(acc[mt][nt + 1][0] + b210, 0.f), w310, sl1);
                sl1 = fmaf(fmaxf(acc[mt][nt + 1][1] + b211, 0.f), w311, sl1);
                sh1 = fmaf(fmaxf(acc[mt][nt + 1][2] + b210, 0.f), w310, sh1);
                sh1 = fmaf(fmaxf(acc[mt][nt + 1][3] + b211, 0.f), w311, sh1);
            }
            float slo = sl0 + sl1;
            float shi = sh0 + sh1;
            slo += __shfl_xor_sync(0xFFFFFFFFu, slo, 1);
            slo += __shfl_xor_sync(0xFFFFFFFFu, slo, 2);
            shi += __shfl_xor_sync(0xFFFFFFFFu, shi, 1);
            shi += __shfl_xor_sync(0xFFFFFFFFu, shi, 2);
            if (q == 0) {
                int gi = i0 + mt;
                int gjlo = j0 + p;
                int gjhi = gjlo + 8;
                size_t base = ((size_t)((b << 10) + gi)) << 10;
                out[base + gjlo] = (gjlo > gi) ? (slo + b3v) : 0.f;
                out[base + gjhi] = (gjhi > gi) ? (shi + b3v) : 0.f;
            }
        }
        buf ^= 1;
    }

    // -------- reset barrier counters for next graph replay --------
    __syncthreads();
    if (tid == 0) {
        unsigned d = atomicAdd(&g_done, 1u);
        if (d == (unsigned)nblk - 1u) {
            atomicExch(&g_cnt, 0u);
            atomicExch(&g_done, 0u);
            __threadfence();
        }
    }
}

// ---------------------------------------------------------------------------
extern "C" void kernel_launch(void* const* d_in, const int* in_sizes, int n_in,
                              void* d_out, int out_size) {
    const float* x  = (const float*)d_in[0];
    const float* W1 = (const float*)d_in[1];
    const float* b1 = (const float*)d_in[2];
    const float* W2 = (const float*)d_in[3];
    const float* b2 = (const float*)d_in[4];
    const float* W3 = (const float*)d_in[5];
    const float* b3 = (const float*)d_in[6];
    float* out = (float*)d_out;

    static bool attr_set = false;
    if (!attr_set) {
        cudaFuncSetAttribute(fused_kernel,
                             cudaFuncAttributeMaxDynamicSharedMemorySize,
                             SMEM_TOTAL);
        attr_set = true;
    }

    int sms = 148;
    cudaDeviceGetAttribute(&sms, cudaDevAttrMultiProcessorCount, 0);
    if (sms < 148) sms = 148;

    fused_kernel<<<sms, 256, SMEM_TOTAL>>>(x, W1, b1, W2, b2, W3, b3, out);
}

// round 16
// speedup vs baseline: 1.0038x; 1.0038x over previous
#include <cuda_runtime.h>
#include <cuda_fp16.h>
#include <cstdint>

// B=2, N=1024, C=128, H1=128, H2=64
//   aL[b,i,h] = x[b,i]@W1[:C] + b1 ; aR[b,j,h] = x[b,j]@W1[C:]
//   y[b,i,j] = relu(relu(aL_i + aR_j) @ W2 + b2) @ W3 + b3   (j>i else 0)
// R16 = R14 (best, 65.6us: warp-autonomous tiles, w2r nt0..3 in regs)
//   + zero-C first-kstep MMAs (no 128-MOV acc init per tile)   [R15 item 1]
//   + 2-way ILP epilogue                                        [R15 item 3]
// R15's w2r cut (nt0..1) is REVERTED — it added inner-loop LDS and regressed.

#define Bb 2
#define Nn 1024
#define Cc 128
#define H1 128
#define H2 64

#define NACT4 16640    // active 4x16 warp-tiles: 2 * 8320
#define HALF4 8320

__device__ __align__(16) __half2 g_aLh[Bb * Nn * 64];
__device__ __align__(16) __half2 g_aRh[Bb * Nn * 64];
__device__ __align__(16) __half2 g_W2h[H2 * 64];
__device__ unsigned g_cnt = 0u;
__device__ unsigned g_done = 0u;

__device__ __forceinline__ int slotperm(int j) {
    int jj = j & 7;
    return (j & ~7) | (jj < 4 ? (jj << 1) : (((jj - 4) << 1) | 1));
}

__device__ __forceinline__ uint32_t h2_relu_add(uint32_t x, uint32_t y) {
    __half2 a = *reinterpret_cast<__half2*>(&x);
    __half2 b = *reinterpret_cast<__half2*>(&y);
    __half2 r = __hmax2(__hadd2(a, b), __float2half2_rn(0.f));
    return *reinterpret_cast<uint32_t*>(&r);
}

__device__ __forceinline__ void mma_f16(float c[4], const uint32_t a[4],
                                        uint32_t b0, uint32_t b1) {
    asm volatile(
        "mma.sync.aligned.m16n8k16.row.col.f32.f16.f16.f32 "
        "{%0,%1,%2,%3},{%4,%5,%6,%7},{%8,%9},{%0,%1,%2,%3};"
        : "+f"(c[0]), "+f"(c[1]), "+f"(c[2]), "+f"(c[3])
        : "r"(a[0]), "r"(a[1]), "r"(a[2]), "r"(a[3]), "r"(b0), "r"(b1));
}

// first-kstep variant: D = A*B + 0 (writes acc; no prior zero init)
__device__ __forceinline__ void mma_f16_zero(float c[4], const uint32_t a[4],
                                             uint32_t b0, uint32_t b1) {
    asm volatile(
        "mma.sync.aligned.m16n8k16.row.col.f32.f16.f16.f32 "
        "{%0,%1,%2,%3},{%4,%5,%6,%7},{%8,%9},{%10,%10,%10,%10};"
        : "=f"(c[0]), "=f"(c[1]), "=f"(c[2]), "=f"(c[3])
        : "r"(a[0]), "r"(a[1]), "r"(a[2]), "r"(a[3]), "r"(b0), "r"(b1),
          "f"(0.f));
}

__device__ __forceinline__ uint32_t smem_u32(const void* p) {
    uint32_t a;
    asm("{ .reg .u64 t; cvta.to.shared.u64 t, %1; cvt.u32.u64 %0, t; }"
        : "=r"(a) : "l"(p));
    return a;
}
__device__ __forceinline__ void cpasync16(uint32_t dst, const void* src) {
    asm volatile("cp.async.cg.shared.global [%0], [%1], 16;"
                 :: "r"(dst), "l"(src));
}
#define CP_COMMIT() asm volatile("cp.async.commit_group;" ::: "memory")
#define CP_WAIT1()  asm volatile("cp.async.wait_group 1;" ::: "memory")

#define AR_STRIDE 34
#define W2_STRIDE 34

#define SM_B2_OFF   17408
#define SM_W3_OFF   17664
#define SM_WARP_OFF 17920
#define WARP_BYTES  10752
#define SMEM_TOTAL  (SM_WARP_OFF + 8 * WARP_BYTES)   // 103936

__device__ __forceinline__ void decode4(int a, int& b, int& i0, int& j0) {
    b = (a >= HALF4);
    int aa = a - (b ? HALF4 : 0);
    int g = (int)((258.f - sqrtf(66564.f - 8.f * (float)aa)) * 0.25f);
    if (g < 0) g = 0;
    if (g > 63) g = 63;
    while (g < 63 && 258 * (g + 1) - 2 * (g + 1) * (g + 1) <= aa) g++;
    while (g > 0 && 258 * g - 2 * g * g > aa) g--;
    int rem = aa - (258 * g - 2 * g * g);
    int cnt = 64 - g;
    int io = rem / cnt;
    j0 = (g + rem - io * cnt) << 4;
    i0 = (g << 4) + (io << 2);
}

__global__ void __launch_bounds__(256)
fused_kernel(const float* __restrict__ x,
             const float* __restrict__ W1,
             const float* __restrict__ b1,
             const float* __restrict__ W2,
             const float* __restrict__ b2,
             const float* __restrict__ W3,
             const float* __restrict__ b3,
             float* __restrict__ out) {
    extern __shared__ char smraw[];

    const int tid = threadIdx.x;
    const int bid = blockIdx.x;
    const int nblk = gridDim.x;
    const int wid = tid >> 5;
    const int lane = tid & 31;
    const int p = lane >> 2;
    const int q = lane & 3;

    // ======================= PHASE A: prep =======================
    {
        float* sx = (float*)smraw;               // [14][128]
        float* res = (float*)(smraw + 7168);     // [14][256]
        const int r0 = bid * 14;
        const int nrows = min(14, Bb * Nn - r0);

        if (nrows > 0) {
            const float4* x4 = (const float4*)x;
            const int nchunks = nrows * 32;
#pragma unroll
            for (int u = 0; u < 2; u++) {
                int c = tid + 256 * u;
                if (c < nchunks)
                    ((float4*)sx)[c] = x4[r0 * 32 + c];
            }
            __syncthreads();

            const int side = tid >> 7;
            const int h = tid & 127;
            const float* Wp = W1 + (side ? (Cc * H1 + h) : h);
            float acc[14];
            const float init = side ? 0.f : b1[h];
#pragma unroll
            for (int r = 0; r < 14; r++) acc[r] = init;

#pragma unroll 4
            for (int c = 0; c < Cc; c += 4) {
                float w0 = __ldg(&Wp[(c + 0) * H1]);
                float w1 = __ldg(&Wp[(c + 1) * H1]);
                float w2 = __ldg(&Wp[(c + 2) * H1]);
                float w3 = __ldg(&Wp[(c + 3) * H1]);
#pragma unroll
                for (int r = 0; r < 14; r++) {
                    const float* sxr = sx + r * Cc + c;
                    float4 sv = *(const float4*)sxr;
                    float a = acc[r];
                    a = fmaf(sv.x, w0, a);
                    a = fmaf(sv.y, w1, a);
                    a = fmaf(sv.z, w2, a);
                    a = fmaf(sv.w, w3, a);
                    acc[r] = a;
                }
            }
#pragma unroll
            for (int r = 0; r < 14; r++) res[r * 256 + side * 128 + h] = acc[r];
            __syncthreads();

#pragma unroll
            for (int u = 0; u < 7; u++) {
                int idx = tid + 256 * u;
                int row = idx >> 7;
                if (row < nrows) {
                    int rem = idx & 127;
                    int sd = rem >> 6;
                    int j = rem & 63;
                    __half2 v = __floats2half2_rn(res[row * 256 + sd * 128 + 2 * j],
                                                  res[row * 256 + sd * 128 + 2 * j + 1]);
                    (sd ? g_aRh : g_aLh)[(size_t)(r0 + row) * 64 + slotperm(j)] = v;
                }
            }
        } else {
            for (int idx = (bid - 147) * 256 + tid; idx < H2 * 64;
                 idx += (nblk - 147) * 256) {
                int n = idx >> 6;
                int j = idx & 63;
                g_W2h[n * 64 + slotperm(j)] =
                    __floats2half2_rn(W2[(2 * j) * H2 + n],
                                      W2[(2 * j + 1) * H2 + n]);
            }
        }

        // zero masked region (rows: j < 16*(i>>4))
        {
            float4* out4 = (float4*)out;
            const float4 z4 = make_float4(0.f, 0.f, 0.f, 0.f);
            for (int r = bid; r < Bb * Nn; r += nblk) {
                int i = r & (Nn - 1);
                int n4 = 4 * (i >> 4);
                float4* dst = out4 + ((size_t)r << 8);
                for (int c = tid; c < n4; c += 256) dst[c] = z4;
            }
        }
    }

    // =================== grid barrier (spin, self-resetting) ===================
    __threadfence();
    __syncthreads();
    if (tid == 0) {
        atomicAdd(&g_cnt, 1u);
        while (atomicAdd(&g_cnt, 0u) < (unsigned)nblk) __nanosleep(64);
    }
    __syncthreads();

    // ======================= PHASE B: warp-autonomous pair GEMM =======================
    uint2* w2s = (uint2*)smraw;
    float* b2s = (float*)(smraw + SM_B2_OFF);
    float* w3s = (float*)(smraw + SM_W3_OFF);

    {
        const uint2* gW2 = (const uint2*)g_W2h;
        for (int i = tid; i < H2 * 32; i += 256) {
            int r = i >> 5, c = i & 31;
            w2s[r * W2_STRIDE + c] = gW2[i];
        }
        if (tid < H2) {
            b2s[tid] = b2[tid];
            w3s[tid] = W3[tid];
        }
    }
    const float b3v = __ldg(&b3[0]);
    __syncthreads();      // last CTA-wide barrier; warps free-run after this

    // persistent W2 fragments nt 0..3 (64 regs) — R14 config
    uint32_t w2r[8][4][2];
#pragma unroll
    for (int ks = 0; ks < 8; ks++)
#pragma unroll
        for (int ntl = 0; ntl < 4; ntl++) {
            uint2 bb = w2s[(ntl * 8 + p) * W2_STRIDE + 4 * ks + q];
            w2r[ks][ntl][0] = bb.x;
            w2r[ks][ntl][1] = bb.y;
        }

    char* wb = smraw + SM_WARP_OFF + wid * WARP_BYTES;
    const uint32_t wL32 = smem_u32(wb);
    const uint32_t wR32 = wL32 + 2048;
    uint2* aLbase = (uint2*)wb;
    uint2* aRbase = (uint2*)(wb + 2048);

    auto issue_stage = [&](int bf, int b, int i0, int j0) {
        const uint4* srcL = (const uint4*)(g_aLh + ((size_t)((b << 10) + i0) << 6));
        const uint4* srcR = (const uint4*)(g_aRh + ((size_t)((b << 10) + j0) << 6));
        uint32_t dL = wL32 + (uint32_t)bf * 1024u;
        uint32_t dR = wR32 + (uint32_t)bf * 4352u;
        cpasync16(dL + (uint32_t)lane * 16u, srcL + lane);
        cpasync16(dL + (uint32_t)(lane + 32) * 16u, srcL + lane + 32);
#pragma unroll
        for (int u = 0; u < 8; u++) {
            int c = lane + 32 * u;
            int row = c >> 4, col = c & 15;
            cpasync16(dR + (uint32_t)(row * 17 + col) * 16u, srcR + c);
        }
    };

    int a = bid * 8 + wid;
    const int astep = nblk * 8;
    int buf = 0;
    int curB = 0, curI0 = 0, curJ0 = 0;
    if (a < NACT4) {
        decode4(a, curB, curI0, curJ0);
        issue_stage(0, curB, curI0, curJ0);
    }
    CP_COMMIT();

    for (; a < NACT4; a += astep) {
        const int b  = curB;
        const int i0 = curI0;
        const int j0 = curJ0;

        {
            int an = a + astep;
            if (an < NACT4) {
                decode4(an, curB, curI0, curJ0);
                issue_stage(buf ^ 1, curB, curI0, curJ0);
            }
            CP_COMMIT();
        }
        CP_WAIT1();
        __syncwarp();

        const uint2* aLb = aLbase + buf * 128;
        const uint2* aRb = aRbase + buf * 544;

        float acc[4][8][4];   // written by ks=0 zero-C MMAs; no init

        uint2 Rp_c, Rp8_c, La_c0, La_c1, La_c2, La_c3;
        {
            const int kf = q;
            Rp_c  = aRb[p * AR_STRIDE + kf];
            Rp8_c = aRb[(p + 8) * AR_STRIDE + kf];
            La_c0 = aLb[0 * 32 + kf];
            La_c1 = aLb[1 * 32 + kf];
            La_c2 = aLb[2 * 32 + kf];
            La_c3 = aLb[3 * 32 + kf];
        }
#pragma unroll
        for (int ks = 0; ks < 8; ks++) {
            uint2 Rp_n, Rp8_n, La_n0, La_n1, La_n2, La_n3;
            if (ks < 7) {
                const int kf = 4 * (ks + 1) + q;
                Rp_n  = aRb[p * AR_STRIDE + kf];
                Rp8_n = aRb[(p + 8) * AR_STRIDE + kf];
                La_n0 = aLb[0 * 32 + kf];
                La_n1 = aLb[1 * 32 + kf];
                La_n2 = aLb[2 * 32 + kf];
                La_n3 = aLb[3 * 32 + kf];
            }

            uint32_t a4[4][4];
            {
                uint2 Ls[4] = {La_c0, La_c1, La_c2, La_c3};
#pragma unroll
                for (int mt = 0; mt < 4; mt++) {
                    a4[mt][0] = h2_relu_add(Ls[mt].x, Rp_c.x);
                    a4[mt][1] = h2_relu_add(Ls[mt].x, Rp8_c.x);
                    a4[mt][2] = h2_relu_add(Ls[mt].y, Rp_c.y);
                    a4[mt][3] = h2_relu_add(Ls[mt].y, Rp8_c.y);
                }
            }

            if (ks == 0) {
#pragma unroll
                for (int ntl = 0; ntl < 4; ntl++)
#pragma unroll
                    for (int mt = 0; mt < 4; mt++)
                        mma_f16_zero(acc[mt][ntl], a4[mt],
                                     w2r[0][ntl][0], w2r[0][ntl][1]);
#pragma unroll
                for (int ntl = 4; ntl < 8; ntl++) {
                    uint2 bb = w2s[(ntl * 8 + p) * W2_STRIDE + q];
#pragma unroll
                    for (int mt = 0; mt < 4; mt++)
                        mma_f16_zero(acc[mt][ntl], a4[mt], bb.x, bb.y);
                }
            } else {
#pragma unroll
                for (int ntl = 0; ntl < 4; ntl++)
#pragma unroll
                    for (int mt = 0; mt < 4; mt++)
                        mma_f16(acc[mt][ntl], a4[mt],
                                w2r[ks][ntl][0], w2r[ks][ntl][1]);
#pragma unroll
                for (int ntl = 4; ntl < 8; ntl++) {
                    uint2 bb = w2s[(ntl * 8 + p) * W2_STRIDE + 4 * ks + q];
#pragma unroll
                    for (int mt = 0; mt < 4; mt++)
                        mma_f16(acc[mt][ntl], a4[mt], bb.x, bb.y);
                }
            }

            Rp_c = Rp_n; Rp8_c = Rp8_n;
            La_c0 = La_n0; La_c1 = La_n1; La_c2 = La_n2; La_c3 = La_n3;
        }

        // epilogue: y = b3 + sum_g relu(D+b2)*W3 ; 2-way ILP partials
#pragma unroll
        for (int mt = 0; mt < 4; mt++) {
            float sl0 = 0.f, sl1 = 0.f, sh0 = 0.f, sh1 = 0.f;
#pragma unroll
            for (int nt = 0; nt < 8; nt += 2) {
                int g0 = nt * 8 + 2 * q;
                int g1 = (nt + 1) * 8 + 2 * q;
                float b200 = b2s[g0], b201 = b2s[g0 + 1];
                float w300 = w3s[g0], w301 = w3s[g0 + 1];
                float b210 = b2s[g1], b211 = b2s[g1 + 1];
                float w310 = w3s[g1], w311 = w3s[g1 + 1];
                sl0 = fmaf(fmaxf(acc[mt][nt][0] + b200, 0.f), w300, sl0);
                sl0 = fmaf(fmaxf(acc[mt][nt][1] + b201, 0.f), w301, sl0);
                sh0 = fmaf(fmaxf(acc[mt][nt][2] + b200, 0.f), w300, sh0);
                sh0 = fmaf(fmaxf(acc[mt][nt][3] + b201, 0.f), w301, sh0);
                sl1 = fmaf(fmaxf(acc[mt][nt + 1][0] + b210, 0.f), w310, sl1);
                sl1 = fmaf(fmaxf(acc[mt][nt + 1][1] + b211, 0.f), w311, sl1);
                sh1 = fmaf(fmaxf(acc[mt][nt + 1][2] + b210, 0.f), w310, sh1);
                sh1 = fmaf(fmaxf(acc[mt][nt + 1][3] + b211, 0.f), w311, sh1);
            }
            float slo = sl0 + sl1;
            float shi = sh0 + sh1;
            slo += __shfl_xor_sync(0xFFFFFFFFu, slo, 1);
            slo += __shfl_xor_sync(0xFFFFFFFFu, slo, 2);
            shi += __shfl_xor_sync(0xFFFFFFFFu, shi, 1);
            shi += __shfl_xor_sync(0xFFFFFFFFu, shi, 2);
            if (q == 0) {
                int gi = i0 + mt;
                int gjlo = j0 + p;
                int gjhi = gjlo + 8;
                size_t base = ((size_t)((b << 10) + gi)) << 10;
                out[base + gjlo] = (gjlo > gi) ? (slo + b3v) : 0.f;
                out[base + gjhi] = (gjhi > gi) ? (shi + b3v) : 0.f;
            }
        }
        buf ^= 1;
    }

    // -------- reset barrier counters for next graph replay --------
    __syncthreads();
    if (tid == 0) {
        unsigned d = atomicAdd(&g_done, 1u);
        if (d == (unsigned)nblk - 1u) {
            atomicExch(&g_cnt, 0u);
            atomicExch(&g_done, 0u);
            __threadfence();
        }
    }
}

// ---------------------------------------------------------------------------
extern "C" void kernel_launch(void* const* d_in, const int* in_sizes, int n_in,
                              void* d_out, int out_size) {
    const float* x  = (const float*)d_in[0];
    const float* W1 = (const float*)d_in[1];
    const float* b1 = (const float*)d_in[2];
    const float* W2 = (const float*)d_in[3];
    const float* b2 = (const float*)d_in[4];
    const float* W3 = (const float*)d_in[5];
    const float* b3 = (const float*)d_in[6];
    float* out = (float*)d_out;

    static bool attr_set = false;
    if (!attr_set) {
        cudaFuncSetAttribute(fused_kernel,
                             cudaFuncAttributeMaxDynamicSharedMemorySize,
                             SMEM_TOTAL);
        attr_set = true;
    }

    int sms = 148;
    cudaDeviceGetAttribute(&sms, cudaDevAttrMultiProcessorCount, 0);
    if (sms < 148) sms = 148;

    fused_kernel<<<sms, 256, SMEM_TOTAL>>>(x, W1, b1, W2, b2, W3, b3, out);
}

// round 17
// speedup vs baseline: 1.0467x; 1.0428x over previous
#include <cuda_runtime.h>
#include <cuda_fp16.h>
#include <cstdint>

// B=2, N=1024, C=128, H1=128, H2=64
//   aL[b,i,h] = x[b,i]@W1[:C] + b1 ; aR[b,j,h] = x[b,j]@W1[C:]
//   y[b,i,j] = relu(relu(aL_i + aR_j) @ W2 + b2) @ W3 + b3   (j>i else 0)
// R17 = exact R14 (best, 65.6us) with ONE change: triple-buffered warp-private
// staging (prefetch depth 2, cp.async.wait_group 2). R15/R16 micro-tweaks
// (zero-C init, ILP epilogue, w2r cut) all regressed -> reverted wholesale.

#define Bb 2
#define Nn 1024
#define Cc 128
#define H1 128
#define H2 64

#define NACT4 16640    // active 4x16 warp-tiles: 2 * 8320
#define HALF4 8320

__device__ __align__(16) __half2 g_aLh[Bb * Nn * 64];
__device__ __align__(16) __half2 g_aRh[Bb * Nn * 64];
__device__ __align__(16) __half2 g_W2h[H2 * 64];
__device__ unsigned g_cnt = 0u;
__device__ unsigned g_done = 0u;

__device__ __forceinline__ int slotperm(int j) {
    int jj = j & 7;
    return (j & ~7) | (jj < 4 ? (jj << 1) : (((jj - 4) << 1) | 1));
}

__device__ __forceinline__ uint32_t h2_relu_add(uint32_t x, uint32_t y) {
    __half2 a = *reinterpret_cast<__half2*>(&x);
    __half2 b = *reinterpret_cast<__half2*>(&y);
    __half2 r = __hmax2(__hadd2(a, b), __float2half2_rn(0.f));
    return *reinterpret_cast<uint32_t*>(&r);
}

__device__ __forceinline__ void mma_f16(float c[4], const uint32_t a[4],
                                        uint32_t b0, uint32_t b1) {
    asm volatile(
        "mma.sync.aligned.m16n8k16.row.col.f32.f16.f16.f32 "
        "{%0,%1,%2,%3},{%4,%5,%6,%7},{%8,%9},{%0,%1,%2,%3};"
        : "+f"(c[0]), "+f"(c[1]), "+f"(c[2]), "+f"(c[3])
        : "r"(a[0]), "r"(a[1]), "r"(a[2]), "r"(a[3]), "r"(b0), "r"(b1));
}

__device__ __forceinline__ uint32_t smem_u32(const void* p) {
    uint32_t a;
    asm("{ .reg .u64 t; cvta.to.shared.u64 t, %1; cvt.u32.u64 %0, t; }"
        : "=r"(a) : "l"(p));
    return a;
}
__device__ __forceinline__ void cpasync16(uint32_t dst, const void* src) {
    asm volatile("cp.async.cg.shared.global [%0], [%1], 16;"
                 :: "r"(dst), "l"(src));
}
#define CP_COMMIT() asm volatile("cp.async.commit_group;" ::: "memory")
#define CP_WAIT2()  asm volatile("cp.async.wait_group 2;" ::: "memory")

#define AR_STRIDE 34
#define W2_STRIDE 34

#define SM_B2_OFF   17408
#define SM_W3_OFF   17664
#define SM_WARP_OFF 17920
// per-warp: 3 x aL (1024B) + 3 x aR (4352B) = 16128B
#define WARP_BYTES  16128
#define SMEM_TOTAL  (SM_WARP_OFF + 8 * WARP_BYTES)   // 146944

__device__ __forceinline__ void decode4(int a, int& b, int& i0, int& j0) {
    b = (a >= HALF4);
    int aa = a - (b ? HALF4 : 0);
    int g = (int)((258.f - sqrtf(66564.f - 8.f * (float)aa)) * 0.25f);
    if (g < 0) g = 0;
    if (g > 63) g = 63;
    while (g < 63 && 258 * (g + 1) - 2 * (g + 1) * (g + 1) <= aa) g++;
    while (g > 0 && 258 * g - 2 * g * g > aa) g--;
    int rem = aa - (258 * g - 2 * g * g);
    int cnt = 64 - g;
    int io = rem / cnt;
    j0 = (g + rem - io * cnt) << 4;
    i0 = (g << 4) + (io << 2);
}

__global__ void __launch_bounds__(256)
fused_kernel(const float* __restrict__ x,
             const float* __restrict__ W1,
             const float* __restrict__ b1,
             const float* __restrict__ W2,
             const float* __restrict__ b2,
             const float* __restrict__ W3,
             const float* __restrict__ b3,
             float* __restrict__ out) {
    extern __shared__ char smraw[];

    const int tid = threadIdx.x;
    const int bid = blockIdx.x;
    const int nblk = gridDim.x;
    const int wid = tid >> 5;
    const int lane = tid & 31;
    const int p = lane >> 2;
    const int q = lane & 3;

    // ======================= PHASE A: prep =======================
    {
        float* sx = (float*)smraw;               // [14][128]
        float* res = (float*)(smraw + 7168);     // [14][256]
        const int r0 = bid * 14;
        const int nrows = min(14, Bb * Nn - r0);

        if (nrows > 0) {
            const float4* x4 = (const float4*)x;
            const int nchunks = nrows * 32;
#pragma unroll
            for (int u = 0; u < 2; u++) {
                int c = tid + 256 * u;
                if (c < nchunks)
                    ((float4*)sx)[c] = x4[r0 * 32 + c];
            }
            __syncthreads();

            const int side = tid >> 7;
            const int h = tid & 127;
            const float* Wp = W1 + (side ? (Cc * H1 + h) : h);
            float acc[14];
            const float init = side ? 0.f : b1[h];
#pragma unroll
            for (int r = 0; r < 14; r++) acc[r] = init;

#pragma unroll 4
            for (int c = 0; c < Cc; c += 4) {
                float w0 = __ldg(&Wp[(c + 0) * H1]);
                float w1 = __ldg(&Wp[(c + 1) * H1]);
                float w2 = __ldg(&Wp[(c + 2) * H1]);
                float w3 = __ldg(&Wp[(c + 3) * H1]);
#pragma unroll
                for (int r = 0; r < 14; r++) {
                    const float* sxr = sx + r * Cc + c;
                    float4 sv = *(const float4*)sxr;
                    float a = acc[r];
                    a = fmaf(sv.x, w0, a);
                    a = fmaf(sv.y, w1, a);
                    a = fmaf(sv.z, w2, a);
                    a = fmaf(sv.w, w3, a);
                    acc[r] = a;
                }
            }
#pragma unroll
            for (int r = 0; r < 14; r++) res[r * 256 + side * 128 + h] = acc[r];
            __syncthreads();

#pragma unroll
            for (int u = 0; u < 7; u++) {
                int idx = tid + 256 * u;
                int row = idx >> 7;
                if (row < nrows) {
                    int rem = idx & 127;
                    int sd = rem >> 6;
                    int j = rem & 63;
                    __half2 v = __floats2half2_rn(res[row * 256 + sd * 128 + 2 * j],
                                                  res[row * 256 + sd * 128 + 2 * j + 1]);
                    (sd ? g_aRh : g_aLh)[(size_t)(r0 + row) * 64 + slotperm(j)] = v;
                }
            }
        } else {
            for (int idx = (bid - 147) * 256 + tid; idx < H2 * 64;
                 idx += (nblk - 147) * 256) {
                int n = idx >> 6;
                int j = idx & 63;
                g_W2h[n * 64 + slotperm(j)] =
                    __floats2half2_rn(W2[(2 * j) * H2 + n],
                                      W2[(2 * j + 1) * H2 + n]);
            }
        }

        // zero masked region (rows: j < 16*(i>>4))
        {
            float4* out4 = (float4*)out;
            const float4 z4 = make_float4(0.f, 0.f, 0.f, 0.f);
            for (int r = bid; r < Bb * Nn; r += nblk) {
                int i = r & (Nn - 1);
                int n4 = 4 * (i >> 4);
                float4* dst = out4 + ((size_t)r << 8);
                for (int c = tid; c < n4; c += 256) dst[c] = z4;
            }
        }
    }

    // =================== grid barrier (spin, self-resetting) ===================
    __threadfence();
    __syncthreads();
    if (tid == 0) {
        atomicAdd(&g_cnt, 1u);
        while (atomicAdd(&g_cnt, 0u) < (unsigned)nblk) __nanosleep(64);
    }
    __syncthreads();

    // ======================= PHASE B: warp-autonomous pair GEMM =======================
    uint2* w2s = (uint2*)smraw;
    float* b2s = (float*)(smraw + SM_B2_OFF);
    float* w3s = (float*)(smraw + SM_W3_OFF);

    {
        const uint2* gW2 = (const uint2*)g_W2h;
        for (int i = tid; i < H2 * 32; i += 256) {
            int r = i >> 5, c = i & 31;
            w2s[r * W2_STRIDE + c] = gW2[i];
        }
        if (tid < H2) {
            b2s[tid] = b2[tid];
            w3s[tid] = W3[tid];
        }
    }
    const float b3v = __ldg(&b3[0]);
    __syncthreads();      // last CTA-wide barrier; warps free-run after this

    // persistent W2 fragments nt 0..3 (64 regs) — R14 config
    uint32_t w2r[8][4][2];
#pragma unroll
    for (int ks = 0; ks < 8; ks++)
#pragma unroll
        for (int ntl = 0; ntl < 4; ntl++) {
            uint2 bb = w2s[(ntl * 8 + p) * W2_STRIDE + 4 * ks + q];
            w2r[ks][ntl][0] = bb.x;
            w2r[ks][ntl][1] = bb.y;
        }

    char* wb = smraw + SM_WARP_OFF + wid * WARP_BYTES;
    const uint32_t wL32 = smem_u32(wb);
    const uint32_t wR32 = wL32 + 3072u;          // 3 aL bufs of 1024B first
    uint2* aLbase = (uint2*)wb;                  // slot s at +s*1024
    uint2* aRbase = (uint2*)(wb + 3072);         // slot s at +s*4352

    auto issue_stage = [&](int sl, int b, int i0, int j0) {
        const uint4* srcL = (const uint4*)(g_aLh + ((size_t)((b << 10) + i0) << 6));
        const uint4* srcR = (const uint4*)(g_aRh + ((size_t)((b << 10) + j0) << 6));
        uint32_t dL = wL32 + (uint32_t)sl * 1024u;
        uint32_t dR = wR32 + (uint32_t)sl * 4352u;
        cpasync16(dL + (uint32_t)lane * 16u, srcL + lane);
        cpasync16(dL + (uint32_t)(lane + 32) * 16u, srcL + lane + 32);
#pragma unroll
        for (int u = 0; u < 8; u++) {
            int c = lane + 32 * u;
            int row = c >> 4, col = c & 15;
            cpasync16(dR + (uint32_t)(row * 17 + col) * 16u, srcR + c);
        }
    };

    int a = bid * 8 + wid;
    const int astep = nblk * 8;

    // coordinate pipeline: slot s holds tile t, s+1 -> t+1, s+2 -> t+2
    int cB0 = 0, cI0 = 0, cJ0 = 0;   // tile t      (slot sc)
    int cB1 = 0, cI1 = 0, cJ1 = 0;   // tile t+1
    if (a < NACT4) {
        decode4(a, cB0, cI0, cJ0);
        issue_stage(0, cB0, cI0, cJ0);
    }
    CP_COMMIT();
    {
        int a1 = a + astep;
        if (a1 < NACT4) {
            decode4(a1, cB1, cI1, cJ1);
            issue_stage(1, cB1, cI1, cJ1);
        }
        CP_COMMIT();
    }

    int sc = 0;   // compute slot for tile t
    for (; a < NACT4; a += astep) {
        const int b  = cB0;
        const int i0 = cI0;
        const int j0 = cJ0;

        // prefetch tile t+2 into slot (sc+2)%3
        {
            int a2 = a + 2 * astep;
            if (a2 < NACT4) {
                int b2n, i2n, j2n;
                decode4(a2, b2n, i2n, j2n);
                int s2 = sc + 2;
                if (s2 >= 3) s2 -= 3;
                issue_stage(s2, b2n, i2n, j2n);
                // shift coordinate pipeline
                cB0 = cB1; cI0 = cI1; cJ0 = cJ1;
                cB1 = b2n; cI1 = i2n; cJ1 = j2n;
            } else {
                cB0 = cB1; cI0 = cI1; cJ0 = cJ1;
            }
            CP_COMMIT();
        }
        CP_WAIT2();        // tile t's group complete; t+1/t+2 may be in flight
        __syncwarp();

        const uint2* aLb = aLbase + sc * 128;
        const uint2* aRb = aRbase + sc * 544;

        float acc[4][8][4];
#pragma unroll
        for (int mt = 0; mt < 4; mt++)
#pragma unroll
            for (int nt = 0; nt < 8; nt++)
#pragma unroll
                for (int e = 0; e < 4; e++) acc[mt][nt][e] = 0.f;

        // kstep loop with one-stage register pipeline (R14 body)
        uint2 Rp_c, Rp8_c, La_c0, La_c1, La_c2, La_c3;
        {
            const int kf = q;
            Rp_c  = aRb[p * AR_STRIDE + kf];
            Rp8_c = aRb[(p + 8) * AR_STRIDE + kf];
            La_c0 = aLb[0 * 32 + kf];
            La_c1 = aLb[1 * 32 + kf];
            La_c2 = aLb[2 * 32 + kf];
            La_c3 = aLb[3 * 32 + kf];
        }
#pragma unroll
        for (int ks = 0; ks < 8; ks++) {
            uint2 Rp_n, Rp8_n, La_n0, La_n1, La_n2, La_n3;
            if (ks < 7) {
                const int kf = 4 * (ks + 1) + q;
                Rp_n  = aRb[p * AR_STRIDE + kf];
                Rp8_n = aRb[(p + 8) * AR_STRIDE + kf];
                La_n0 = aLb[0 * 32 + kf];
                La_n1 = aLb[1 * 32 + kf];
                La_n2 = aLb[2 * 32 + kf];
                La_n3 = aLb[3 * 32 + kf];
            }

            uint32_t a4[4][4];
            {
                uint2 Ls[4] = {La_c0, La_c1, La_c2, La_c3};
#pragma unroll
                for (int mt = 0; mt < 4; mt++) {
                    a4[mt][0] = h2_relu_add(Ls[mt].x, Rp_c.x);
                    a4[mt][1] = h2_relu_add(Ls[mt].x, Rp8_c.x);
                    a4[mt][2] = h2_relu_add(Ls[mt].y, Rp_c.y);
                    a4[mt][3] = h2_relu_add(Ls[mt].y, Rp8_c.y);
                }
            }

#pragma unroll
            for (int ntl = 0; ntl < 4; ntl++)
#pragma unroll
                for (int mt = 0; mt < 4; mt++)
                    mma_f16(acc[mt][ntl], a4[mt],
                            w2r[ks][ntl][0], w2r[ks][ntl][1]);
#pragma unroll
            for (int ntl = 4; ntl < 8; ntl++) {
                uint2 bb = w2s[(ntl * 8 + p) * W2_STRIDE + 4 * ks + q];
#pragma unroll
                for (int mt = 0; mt < 4; mt++)
                    mma_f16(acc[mt][ntl], a4[mt], bb.x, bb.y);
            }

            Rp_c = Rp_n; Rp8_c = Rp8_n;
            La_c0 = La_n0; La_c1 = La_n1; La_c2 = La_n2; La_c3 = La_n3;
        }

        // epilogue (R14 form)
#pragma unroll
        for (int mt = 0; mt < 4; mt++) {
            float slo = 0.f, shi = 0.f;
#pragma unroll
            for (int nt = 0; nt < 8; nt++) {
                int g0 = nt * 8 + 2 * q;
                float b20 = b2s[g0], b21 = b2s[g0 + 1];
                float w30 = w3s[g0], w31 = w3s[g0 + 1];
                slo = fmaf(fmaxf(acc[mt][nt][0] + b20, 0.f), w30, slo);
                slo = fmaf(fmaxf(acc[mt][nt][1] + b21, 0.f), w31, slo);
                shi = fmaf(fmaxf(acc[mt][nt][2] + b20, 0.f), w30, shi);
                shi = fmaf(fmaxf(acc[mt][nt][3] + b21, 0.f), w31, shi);
            }
            slo += __shfl_xor_sync(0xFFFFFFFFu, slo, 1);
            slo += __shfl_xor_sync(0xFFFFFFFFu, slo, 2);
            shi += __shfl_xor_sync(0xFFFFFFFFu, shi, 1);
            shi += __shfl_xor_sync(0xFFFFFFFFu, shi, 2);
            if (q == 0) {
                int gi = i0 + mt;
                int gjlo = j0 + p;
                int gjhi = gjlo + 8;
                size_t base = ((size_t)((b << 10) + gi)) << 10;
                out[base + gjlo] = (gjlo > gi) ? (slo + b3v) : 0.f;
                out[base + gjhi] = (gjhi > gi) ? (shi + b3v) : 0.f;
            }
        }
        sc++;
        if (sc >= 3) sc = 0;
    }

    // -------- reset barrier counters for next graph replay --------
    __syncthreads();
    if (tid == 0) {
        unsigned d = atomicAdd(&g_done, 1u);
        if (d == (unsigned)nblk - 1u) {
            atomicExch(&g_cnt, 0u);
            atomicExch(&g_done, 0u);
            __threadfence();
        }
    }
}

// ---------------------------------------------------------------------------
extern "C" void kernel_launch(void* const* d_in, const int* in_sizes, int n_in,
                              void* d_out, int out_size) {
    const float* x  = (const float*)d_in[0];
    const float* W1 = (const float*)d_in[1];
    const float* b1 = (const float*)d_in[2];
    const float* W2 = (const float*)d_in[3];
    const float* b2 = (const float*)d_in[4];
    const float* W3 = (const float*)d_in[5];
    const float* b3 = (const float*)d_in[6];
    float* out = (float*)d_out;

    static bool attr_set = false;
    if (!attr_set) {
        cudaFuncSetAttribute(fused_kernel,
                             cudaFuncAttributeMaxDynamicSharedMemorySize,
                             SMEM_TOTAL);
        attr_set = true;
    }

    int sms = 148;
    cudaDeviceGetAttribute(&sms, cudaDevAttrMultiProcessorCount, 0);
    if (sms < 148) sms = 148;

    fused_kernel<<<sms, 256, SMEM_TOTAL>>>(x, W1, b1, W2, b2, W3, b3, out);
}